// round 17
// baseline (speedup 1.0000x reference)
#include <cuda_runtime.h>
#include <cstdint>

typedef unsigned long long ull;

#define TPB   512
#define NB    8
#define R_    16
#define D_    1024

// ---- packed f32x2 helpers ----
__device__ __forceinline__ ull ffma2(ull a, ull b, ull c) {
    ull d;
    asm("fma.rn.f32x2 %0, %1, %2, %3;" : "=l"(d) : "l"(a), "l"(b), "l"(c));
    return d;
}
__device__ __forceinline__ ull fmul2(ull a, ull b) {
    ull d;
    asm("mul.rn.f32x2 %0, %1, %2;" : "=l"(d) : "l"(a), "l"(b));
    return d;
}
__device__ __forceinline__ ull fadd2(ull a, ull b) {
    ull d;
    asm("add.rn.f32x2 %0, %1, %2;" : "=l"(d) : "l"(a), "l"(b));
    return d;
}
__device__ __forceinline__ float lo_(ull v) { return __int_as_float((int)(unsigned)(v & 0xffffffffull)); }
__device__ __forceinline__ float hi_(ull v) { return __int_as_float((int)(unsigned)(v >> 32)); }
__device__ __forceinline__ ull   dup_(float v) {
    ull d;
    asm("mov.b64 %0, {%1, %1};" : "=l"(d) : "r"(__float_as_uint(v)));
    return d;
}
__device__ __forceinline__ ull pack2_(float l, float h) {
    ull d;
    asm("mov.b64 %0, {%1, %2};" : "=l"(d) : "r"(__float_as_uint(l)), "r"(__float_as_uint(h)));
    return d;
}
__device__ __forceinline__ ull ldg64(const void* p) {
    ull v;
    asm("ld.global.nc.u64 %0, [%1];" : "=l"(v) : "l"(p));
    return v;
}
__device__ __forceinline__ void stcs64(void* p, ull a) {
    asm volatile("st.global.cs.u64 [%0], %1;" :: "l"(p), "l"(a));
}
__device__ __forceinline__ unsigned sptr(const void* p) {
    return (unsigned)__cvta_generic_to_shared(p);
}
__device__ __forceinline__ void cpa8(unsigned dst, const void* src) {
    asm volatile("cp.async.ca.shared.global [%0], [%1], 8;" :: "r"(dst), "l"(src));
}

// ---- dynamic smem layout (per CTA, ~107 KB → 2 CTAs/SM) ----
#define XS_OFF   0                       // ull   [2][NB][TPB]        65536 B
#define REDP_OFF 65536                   // ull   [NB][TPB]  (x2,xy)  32768 B
#define REDY_OFF 98304                   // float [NB][TPB/2] (y2)     8192 B
#define SB_OFF   106496                  // ull   [2][NB][R_]          2048 B
#define SIDX_OFF 108544                  // int   [2][NB]                64 B
#define SCX_OFF  108608                  // ull   [NB]                   64 B
#define SCY_OFF  108672                  // ull   [NB]                   64 B
#define SMEM_TOTAL 108736

__global__ __launch_bounds__(TPB, 2)
void rlora_kernel(const int*   __restrict__ indices,
                  const float* __restrict__ baseW,
                  const float* __restrict__ loraA,
                  const float* __restrict__ loraB,
                  float*       __restrict__ out,
                  int n_rows, int nbatch)
{
    extern __shared__ char smem_raw[];
    ull   (*xs)[NB][TPB]   = reinterpret_cast<ull(*)[NB][TPB]>(smem_raw + XS_OFF);
    ull   (*redP)[TPB]     = reinterpret_cast<ull(*)[TPB]>(smem_raw + REDP_OFF);
    float (*redY)[TPB / 2] = reinterpret_cast<float(*)[TPB / 2]>(smem_raw + REDY_OFF);
    ull   (*sb)[NB][R_]    = reinterpret_cast<ull(*)[NB][R_]>(smem_raw + SB_OFF);
    int   (*sidx)[NB]      = reinterpret_cast<int(*)[NB]>(smem_raw + SIDX_OFF);
    ull*  scx              = reinterpret_cast<ull*>(smem_raw + SCX_OFF);
    ull*  scy              = reinterpret_cast<ull*>(smem_raw + SCY_OFF);

    const int tid  = threadIdx.x;
    const int wid  = tid >> 5;
    const int lane = tid & 31;
    const int d0   = tid * 2;            // this lane owns columns d0, d0+1

    // lora_A register-resident: a[r] = A[r][d0:d0+2]  (32 regs)
    ull a[R_];
    #pragma unroll
    for (int r = 0; r < R_; ++r) a[r] = ldg64(loraA + r * D_ + d0);

    const int S    = gridDim.x;
    const int b0   = blockIdx.x;
    const int kmax = (nbatch - b0 + S - 1) / S;

    // ---------------- prologue ----------------
    #pragma unroll
    for (int row = 0; row < NB; ++row) {
        int g = b0 * NB + row;
        if (g < n_rows) {
            int idx = __ldg(indices + g);
            cpa8(sptr(&xs[0][row][tid]), baseW + (size_t)idx * D_ + d0);
        }
    }
    asm volatile("cp.async.commit_group;");
    if (tid < NB) {
        int g = (b0 + S) * NB + tid;
        sidx[1][tid] = ((b0 + S) < nbatch && g < n_rows) ? __ldg(indices + g) : -1;
    }
    if (tid < NB * R_) {
        int row = tid >> 4, r = tid & 15;
        int g = b0 * NB + row;
        sb[0][row][r] = (g < n_rows)
            ? dup_(0.1f * __ldg(loraB + (size_t)__ldg(indices + g) * R_ + r)) : 0ull;
    }
    __syncthreads();

    for (int k = 0; k < kmax; ++k) {
        const int  buf      = k & 1;
        const bool havenext = (k + 1) < kmax;

        // ---- step 1: cp.async batch k+1 into xs[buf^1] ----
        #pragma unroll
        for (int row = 0; row < NB; ++row) {
            int idx = havenext ? sidx[(k + 1) & 1][row] : -1;
            if (idx >= 0)
                cpa8(sptr(&xs[buf ^ 1][row][tid]), baseW + (size_t)idx * D_ + d0);
        }
        asm volatile("cp.async.commit_group;");

        // ---- step 2: stage sidx(batch k+2) -> slot k&1 ----
        if (tid < NB) {
            long long g = (long long)(b0 + (k + 2) * S) * NB + tid;
            sidx[buf][tid] = ((k + 2) < kmax && g < n_rows) ? __ldg(indices + g) : -1;
        }
        // ---- step 3: stage sb(batch k+1) -> sb[buf^1] ----
        if (tid < NB * R_) {
            int row = tid >> 4, r = tid & 15;
            int idx = havenext ? sidx[(k + 1) & 1][row] : -1;
            sb[buf ^ 1][row][r] = (idx >= 0)
                ? dup_(0.1f * __ldg(loraB + (size_t)idx * R_ + r)) : 0ull;
        }

        // ---- step 4: batch k copies complete (own slices only) ----
        asm volatile("cp.async.wait_group 1;" ::: "memory");

        // ---- step 5: delta + partials (one y2 prefold shuffle) ----
        ull dvk[NB];
        #pragma unroll
        for (int row = 0; row < NB; ++row) {
            ull xv = xs[buf][row][tid];            // this thread's own copy

            const ulonglong2* bp = reinterpret_cast<const ulonglong2*>(sb[buf][row]);
            ulonglong2 b01 = bp[0];
            ull acc0 = fmul2(b01.x, a[0]);
            ull acc1 = fmul2(b01.y, a[1]);
            #pragma unroll
            for (int kk = 1; kk < R_ / 2; ++kk) {
                ulonglong2 b = bp[kk];
                acc0 = ffma2(b.x, a[2 * kk],     acc0);
                acc1 = ffma2(b.y, a[2 * kk + 1], acc1);
            }
            ull dv = fadd2(acc0, acc1);
            dvk[row] = dv;

            float xl = lo_(xv), xh = hi_(xv);
            float yl = lo_(dv), yh = hi_(dv);
            float x2p = fmaf(xl, xl, xh * xh);
            float xyp = fmaf(xl, yl, xh * yh);
            float y2p = fmaf(yl, yl, yh * yh);

            redP[row][tid] = pack2_(x2p, xyp);     // STS.64
            y2p += __shfl_xor_sync(0xffffffffu, y2p, 16);
            if (lane < 16) redY[row][wid * 16 + lane] = y2p;
        }
        __syncthreads();

        // ---- step 6: warp w (< NB) reduces row w + epilogue ----
        if (wid < NB) {
            const ulonglong2* pP = reinterpret_cast<const ulonglong2*>(redP[wid]);
            ulonglong2 u0 = pP[lane],       u1 = pP[lane + 32],
                       u2 = pP[lane + 64],  u3 = pP[lane + 96],
                       u4 = pP[lane + 128], u5 = pP[lane + 160],
                       u6 = pP[lane + 192], u7 = pP[lane + 224];
            ull sp = fadd2(fadd2(fadd2(fadd2(u0.x, u0.y), fadd2(u1.x, u1.y)),
                                 fadd2(fadd2(u2.x, u2.y), fadd2(u3.x, u3.y))),
                           fadd2(fadd2(fadd2(u4.x, u4.y), fadd2(u5.x, u5.y)),
                                 fadd2(fadd2(u6.x, u6.y), fadd2(u7.x, u7.y))));

            const ulonglong2* pY = reinterpret_cast<const ulonglong2*>(redY[wid]);
            ulonglong2 w0 = pY[lane], w1 = pY[lane + 32];
            ull sy2 = fadd2(fadd2(w0.x, w0.y), fadd2(w1.x, w1.y));

            float a0 = lo_(sp), a1 = hi_(sp);
            float s2 = lo_(sy2) + hi_(sy2);
            #pragma unroll
            for (int off = 16; off > 0; off >>= 1) {
                a0 += __shfl_xor_sync(0xffffffffu, a0, off);
                a1 += __shfl_xor_sync(0xffffffffu, a1, off);
                s2 += __shfl_xor_sync(0xffffffffu, s2, off);
            }
            if (lane == 0) {
                const float MAXN = 1.0f - 1e-5f;
                const float EPSN = 1e-5f;
                float x2 = a0, xy = a1, y2 = s2;

                float nx = sqrtf(x2);
                float sx = (nx > MAXN) ? __fdividef(MAXN, fmaxf(nx, EPSN)) : 1.0f;
                float ny = sqrtf(y2);
                float sy = (ny > MAXN) ? __fdividef(MAXN, fmaxf(ny, EPSN)) : 1.0f;

                float X2 = sx * sx * x2;
                float Y2 = sy * sy * y2;
                float XY = sx * sy * xy;

                float A_  = 1.0f + 2.0f * XY + Y2;
                float B_  = 1.0f - X2;
                float den = fmaxf(1.0f + 2.0f * XY + X2 * Y2, 1e-15f);

                float n2 = (A_ * A_ * X2 + 2.0f * A_ * B_ * XY + B_ * B_ * Y2)
                           / (den * den);
                float no = sqrtf(fmaxf(n2, 0.0f));
                float sf = (no > MAXN) ? __fdividef(MAXN, fmaxf(no, EPSN)) : 1.0f;

                scx[wid] = dup_(__fdividef(sf * A_ * sx, den));
                scy[wid] = dup_(__fdividef(sf * B_ * sy, den));
            }
        }
        __syncthreads();

        // ---- step 7: store batch k (x re-read from smem; slot recycled next iter) ----
        const long long row0 = (long long)(b0 + k * S) * NB;
        float* op = out + (size_t)row0 * D_ + d0;
        #pragma unroll
        for (int row = 0; row < NB; ++row) {
            if (row0 + row < n_rows) {
                ull xv = xs[buf][row][tid];
                ull o  = ffma2(scx[row], xv, fmul2(scy[row], dvk[row]));
                stcs64(op, o);
            }
            op += D_;
        }
    }
}

extern "C" void kernel_launch(void* const* d_in, const int* in_sizes, int n_in,
                              void* d_out, int out_size)
{
    const int*   indices = (const int*)  d_in[0];
    const float* baseW   = (const float*)d_in[1];
    const float* loraA   = (const float*)d_in[2];
    const float* loraB   = (const float*)d_in[3];
    float*       out     = (float*)d_out;

    int n_rows = in_sizes[0];                    // 32768
    int nbatch = (n_rows + NB - 1) / NB;         // 4096
    int grid   = nbatch < 2 * 148 ? nbatch : 2 * 148;   // 2 CTAs/SM

    cudaFuncSetAttribute(rlora_kernel,
                         cudaFuncAttributeMaxDynamicSharedMemorySize, SMEM_TOTAL);
    rlora_kernel<<<grid, TPB, SMEM_TOTAL>>>(indices, baseW, loraA, loraB, out,
                                            n_rows, nbatch);
}